// round 17
// baseline (speedup 1.0000x reference)
#include <cuda_runtime.h>
#include <cuda_fp16.h>
#include <math.h>
#include <stdint.h>

// Scratch (no allocations). Zero-initialized; last block resets for replay.
static __device__ double g_slots[32 * 32];
static __device__ unsigned int g_count;

#define LOG2_1P1 0.13750352374993502f   // log2(1.1)
#define BIGC     1.099511627776e12f     // 2^40 (exact power of two)

#define ROWS    1024                     // rows per pipeline stage
#define THREADS 256
#define STAGES  3

#define PT_BYTES (ROWS * 12u)            // 12288
#define OT_BYTES (ROWS * 4u)             // 4096
#define ST_BYTES (2u * PT_BYTES + OT_BYTES)
#define DYN_SMEM (STAGES * (2u * PT_BYTES + OT_BYTES))   // 86016

__device__ __forceinline__ float ex2f(float x) {
    float r; asm("ex2.approx.f32 %0, %1;" : "=f"(r) : "f"(x)); return r;
}
__device__ __forceinline__ float rcpf(float x) {
    float r; asm("rcp.approx.f32 %0, %1;" : "=f"(r) : "f"(x)); return r;
}

// Paired |cnt(p)-cnt(t)| for TWO rows at once: lanes = (rowA, rowB).
__device__ __forceinline__ void cnt_pair(float pa, float pb, float ta, float tb,
                                         __half2 h0, __half2 h1, __half2 h2,
                                         __half2 h3, __half2 h4,
                                         float& da, float& db) {
    __half2 P = __floats2half2_rn(pa, pb);
    __half2 T = __floats2half2_rn(ta, tb);
    __half2 cp =           __hge2(P, h0);
    cp = __hadd2(cp, __hge2(P, h1));
    cp = __hadd2(cp, __hge2(P, h2));
    cp = __hadd2(cp, __hge2(P, h3));
    cp = __hadd2(cp, __hge2(P, h4));
    __half2 ct =           __hge2(T, h0);
    ct = __hadd2(ct, __hge2(T, h1));
    ct = __hadd2(ct, __hge2(T, h2));
    ct = __hadd2(ct, __hge2(T, h3));
    ct = __hadd2(ct, __hge2(T, h4));
    __half2 d = __hsub2(cp, ct);
    uint32_t du = (*reinterpret_cast<uint32_t*>(&d)) & 0x7fff7fffu;  // |.| both
    __half2 dh = *reinterpret_cast<__half2*>(&du);
    da = __low2float(dh);
    db = __high2float(dh);
}

// total weight (1 + w_mid), predicate-free closed form (exact f32):
__device__ __forceinline__ float wmid1(float p, float t,
                                       float inv_a, float inv_cb, float c2,
                                       float inv_d) {
    float u = __saturatef(t * inv_a);
    float v = __saturatef(fmaf(t, -inv_cb, c2));
    float wlow = fminf(u, v);
    float e2 = ex2f(fmaf(t, -inv_d, 1.0f));
    float pneg = __saturatef(p * -BIGC);
    return wlow + fminf(e2, 1.0f) + pneg;
}

// Loss for TWO rows (A, B) with paired fp16 classification.
__device__ __forceinline__ void row_pair_loss(
    float phA, float thA, float pcA, float tcA, float pnA, float tnA, int otA,
    float phB, float thB, float pcB, float tcB, float pnB, float tnB, int otB,
    float& accA, float& accB) {
    const __half2 H0 = __float2half2_rn(150.f),  H1 = __float2half2_rn(500.f),
                  H2 = __float2half2_rn(1000.f), H3 = __float2half2_rn(1800.f),
                  H4 = __float2half2_rn(2600.f);
    const __half2 C0 = __float2half2_rn(22.f), C1 = __float2half2_rn(35.f),
                  C2 = __float2half2_rn(45.f), C3 = __float2half2_rn(55.f),
                  C4 = __float2half2_rn(65.f);
    const __half2 N0 = __float2half2_rn(0.2f), N1 = __float2half2_rn(0.5f),
                  N2 = __float2half2_rn(1.0f), N3 = __float2half2_rn(1.5f),
                  N4 = __float2half2_rn(2.0f);

    float dA, dB;
    // ---- head: a=80 b=1500 c=1750 d=2000
    cnt_pair(phA, phB, thA, thB, H0, H1, H2, H3, H4, dA, dB);
    accA += fabsf(phA - thA) * (ex2f(dA * LOG2_1P1)
            * wmid1(phA, thA, 1.0f/80.f, 1.0f/250.f, 7.0f, 1.0f/2000.f));
    accB += fabsf(phB - thB) * (ex2f(dB * LOG2_1P1)
            * wmid1(phB, thB, 1.0f/80.f, 1.0f/250.f, 7.0f, 1.0f/2000.f));

    // ---- chest: thr {22..65}*cs == x/cs vs fixed thr; a=10 b=75 c=85 d=100
    float icsA = rcpf(fmaf((float)otA, 0.1f, 0.8f));
    float icsB = rcpf(fmaf((float)otB, 0.1f, 0.8f));
    cnt_pair(pcA * icsA, pcB * icsB, tcA * icsA, tcB * icsB,
             C0, C1, C2, C3, C4, dA, dB);
    accA += fabsf(pcA - tcA) * (ex2f(dA * LOG2_1P1)
            * wmid1(pcA, tcA, 1.0f/10.f, 1.0f/10.f, 8.5f, 1.0f/100.f));
    accB += fabsf(pcB - tcB) * (ex2f(dB * LOG2_1P1)
            * wmid1(pcB, tcB, 1.0f/10.f, 1.0f/10.f, 8.5f, 1.0f/100.f));

    // ---- neck: a=0.15 b=1.5 c=1.7 d=1.9
    cnt_pair(pnA, pnB, tnA, tnB, N0, N1, N2, N3, N4, dA, dB);
    accA += fabsf(pnA - tnA) * (ex2f(dA * LOG2_1P1)
            * wmid1(pnA, tnA, 1.0f/0.15f, 5.0f, 8.5f, 1.0f/1.9f));
    accB += fabsf(pnB - tnB) * (ex2f(dB * LOG2_1P1)
            * wmid1(pnB, tnB, 1.0f/0.15f, 5.0f, 8.5f, 1.0f/1.9f));
}

__device__ __forceinline__ void bulk_cp(unsigned dst, const char* src,
                                        unsigned bytes, unsigned mb) {
    asm volatile(
        "cp.async.bulk.shared::cta.global.mbarrier::complete_tx::bytes "
        "[%0], [%1], %2, [%3];"
        :: "r"(dst), "l"(src), "r"(bytes), "r"(mb) : "memory");
}
__device__ __forceinline__ void mbar_expect(unsigned mb, unsigned bytes) {
    asm volatile("mbarrier.arrive.expect_tx.shared.b64 _, [%0], %1;"
                 :: "r"(mb), "r"(bytes) : "memory");
}
__device__ __forceinline__ void mbar_wait(unsigned mb, unsigned phase) {
    asm volatile(
        "{\n\t"
        ".reg .pred P;\n\t"
        "W%=:\n\t"
        "mbarrier.try_wait.parity.acquire.cta.shared::cta.b64 P, [%0], %1, 0x989680;\n\t"
        "@!P bra W%=;\n\t"
        "}"
        :: "r"(mb), "r"(phase) : "memory");
}

// 3-stage bulk-copy ring with 1024-row stages (dynamic smem): per-iteration
// sync/poll overhead amortized over 2x more rows; paired fp16 classification.
__global__ void __launch_bounds__(THREADS)
k_loss(const char* __restrict__ pred_b, const char* __restrict__ true_b,
       const char* __restrict__ ot_b,
       const float* __restrict__ pred, const float* __restrict__ truep,
       const int* __restrict__ ot,
       float* __restrict__ out,
       long long NST, long long n_tail, long long B, unsigned int n_blocks) {
    extern __shared__ __align__(16) char dyn[];
    char* base_p = dyn;                               // STAGES * PT_BYTES
    char* base_t = dyn + STAGES * PT_BYTES;           // STAGES * PT_BYTES
    char* base_o = dyn + 2 * STAGES * PT_BYTES;       // STAGES * OT_BYTES

    __shared__ alignas(8) unsigned long long mbar_store[STAGES];
    __shared__ float shred[8];

    unsigned mb[STAGES];
    #pragma unroll
    for (int i = 0; i < STAGES; i++)
        mb[i] = (unsigned)__cvta_generic_to_shared(&mbar_store[i]);

    if (threadIdx.x == 0) {
        #pragma unroll
        for (int i = 0; i < STAGES; i++)
            asm volatile("mbarrier.init.shared.b64 [%0], 1;" :: "r"(mb[i]) : "memory");
    }
    __syncthreads();

    const long long G = gridDim.x;
    long long s0 = blockIdx.x;
    const long long niter = (s0 < NST) ? ((NST - 1 - s0) / G + 1) : 0;

    // prologue: fill all stages
    if (threadIdx.x == 0) {
        #pragma unroll
        for (int k = 0; k < STAGES; k++) {
            if (k < niter) {
                long long st_ = s0 + (long long)k * G;
                mbar_expect(mb[k], ST_BYTES);
                bulk_cp((unsigned)__cvta_generic_to_shared(base_p + k * PT_BYTES),
                        pred_b + st_ * (long long)PT_BYTES, PT_BYTES, mb[k]);
                bulk_cp((unsigned)__cvta_generic_to_shared(base_t + k * PT_BYTES),
                        true_b + st_ * (long long)PT_BYTES, PT_BYTES, mb[k]);
                bulk_cp((unsigned)__cvta_generic_to_shared(base_o + k * OT_BYTES),
                        ot_b + st_ * (long long)OT_BYTES, OT_BYTES, mb[k]);
            }
        }
    }

    float acc0 = 0.0f, acc1 = 0.0f, acc2 = 0.0f, acc3 = 0.0f;
    int buf = 0, ph = 0;
    long long scur = s0;
    for (long long it = 0; it < niter; ++it) {
        mbar_wait(mb[buf], (unsigned)ph);

        // conflict-free vector reads: 3x LDS.128 pred, 3x true, 1x int4 ot
        const float4* P4 = (const float4*)(base_p + buf * PT_BYTES);
        const float4* T4 = (const float4*)(base_t + buf * PT_BYTES);
        const int4*   O4 = (const int4*)(base_o + buf * OT_BYTES);
        int tid = threadIdx.x;
        float4 p0 = P4[3*tid+0], p1 = P4[3*tid+1], p2 = P4[3*tid+2];
        float4 t0 = T4[3*tid+0], t1 = T4[3*tid+1], t2 = T4[3*tid+2];
        int4   o  = O4[tid];

        row_pair_loss(p0.x, t0.x, p0.y, t0.y, p0.z, t0.z, o.x,
                      p0.w, t0.w, p1.x, t1.x, p1.y, t1.y, o.y,
                      acc0, acc1);
        row_pair_loss(p1.z, t1.z, p1.w, t1.w, p2.x, t2.x, o.z,
                      p2.y, t2.y, p2.z, t2.z, p2.w, t2.w, o.w,
                      acc2, acc3);

        __syncthreads();   // buffer fully consumed before refill

        long long sfill = scur + (long long)STAGES * G;
        if (threadIdx.x == 0 && it + STAGES < niter) {
            mbar_expect(mb[buf], ST_BYTES);
            bulk_cp((unsigned)__cvta_generic_to_shared(base_p + buf * PT_BYTES),
                    pred_b + sfill * (long long)PT_BYTES, PT_BYTES, mb[buf]);
            bulk_cp((unsigned)__cvta_generic_to_shared(base_t + buf * PT_BYTES),
                    true_b + sfill * (long long)PT_BYTES, PT_BYTES, mb[buf]);
            bulk_cp((unsigned)__cvta_generic_to_shared(base_o + buf * OT_BYTES),
                    ot_b + sfill * (long long)OT_BYTES, OT_BYTES, mb[buf]);
        }
        scur += G;
        if (++buf == STAGES) { buf = 0; ph ^= 1; }
    }

    // tail rows (B % ROWS), one thread of block 0 via global loads
    if (blockIdx.x == 0 && threadIdx.x == 0 && n_tail > 0) {
        long long bse = NST * ROWS;
        for (long long r = bse; r < bse + n_tail; r += 1) {
            float z0 = 0.f, z1 = 0.f;
            row_pair_loss(pred[3*r+0], truep[3*r+0], pred[3*r+1], truep[3*r+1],
                          pred[3*r+2], truep[3*r+2], ot[r],
                          0.f, 0.f, 0.f, 0.f, 0.f, 0.f, 0, z0, z1);
            acc0 += z0;
        }
    }

    // warp + block reduce
    float v = (acc0 + acc1) + (acc2 + acc3);
    #pragma unroll
    for (int o = 16; o > 0; o >>= 1)
        v += __shfl_down_sync(0xFFFFFFFFu, v, o);

    int lane = threadIdx.x & 31, wid = threadIdx.x >> 5;
    if (lane == 0) shred[wid] = v;
    __syncthreads();
    if (wid == 0) {
        v = (lane < 8) ? shred[lane] : 0.0f;
        #pragma unroll
        for (int o = 4; o > 0; o >>= 1)
            v += __shfl_down_sync(0xFFFFFFFFu, v, o);
        if (lane == 0) {
            atomicAdd(&g_slots[(blockIdx.x & 31) * 32], (double)v);
            __threadfence();
            unsigned int done = atomicAdd(&g_count, 1u);
            if (done == n_blocks - 1) {
                double total = 0.0;
                #pragma unroll
                for (int i = 0; i < 32; i++) {
                    volatile double* sp = &g_slots[i * 32];
                    total += *sp;
                }
                out[0] = (float)(total / (double)B);
                #pragma unroll
                for (int i = 0; i < 32; i++)
                    g_slots[i * 32] = 0.0;
                g_count = 0u;
            }
        }
    }
}

extern "C" void kernel_launch(void* const* d_in, const int* in_sizes, int n_in,
                              void* d_out, int out_size) {
    const float* pred = (const float*)d_in[0];
    const float* truep = (const float*)d_in[1];
    const int* ot = (const int*)d_in[2];
    float* out = (float*)d_out;

    long long B = (long long)in_sizes[2];   // rows
    long long NST = B / ROWS;
    long long n_tail = B % ROWS;

    long long blocks = 296;                 // 148 SMs x 2 CTAs, one wave
    if (NST > 0 && blocks > NST) blocks = NST;
    if (blocks < 1) blocks = 1;

    // 84 KB dynamic smem per CTA (idempotent host-side attribute; capture-legal)
    cudaFuncSetAttribute(k_loss, cudaFuncAttributeMaxDynamicSharedMemorySize,
                         (int)DYN_SMEM);

    k_loss<<<(unsigned)blocks, THREADS, DYN_SMEM>>>(
        (const char*)pred, (const char*)truep, (const char*)ot,
        pred, truep, ot, out, NST, n_tail, B, (unsigned)blocks);
}